// round 12
// baseline (speedup 1.0000x reference)
#include <cuda_runtime.h>
#include <cuda_bf16.h>

typedef unsigned int       u32;
typedef unsigned short     u16;
typedef unsigned long long u64;

// ============================================================================
// TT linear via mma.sync (bf16 hi/lo split, 3-product fp32 emulation).
//   L3[k][abc][vwx] = G1*G2*G3 ;  R2[k][de][yz] = G4*G5
//   stage1 (per k): D1'[vwx][(t,de)] = L3k^T[vwx][abc] . X[(t,de)][abc]
//   stage2 (acc k): D2[vwx][t*? yz]  += D1'[vwx][de]   . R2k^T[yz][de]
// Intermediate D1' stays in registers; A2 fragments built with bf16x2 packs.
// ============================================================================

// Padded global operand images (row strides chosen for conflict-free ldmatrix)
__device__ __align__(16) u16 g_L3pad[8][2][17408]; // [k][hi/lo][vwx*136 + abc], 272B rows
__device__ __align__(16) u16 g_R2pad[8][2][1280];  // [k][hi/lo][yz*40 + de],   80B rows

// ---------------- helpers ----------------
__device__ __forceinline__ u32 smem_u32(const void* p) {
    u32 a; asm("{ .reg .u64 t; cvta.to.shared.u64 t, %1; cvt.u32.u64 %0, t; }" : "=r"(a) : "l"(p));
    return a;
}
// pack: low half <- e (first elem), high half <- o (second elem)
__device__ __forceinline__ u32 pack2bf(float e, float o) {
    u32 r; asm("cvt.rn.bf16x2.f32 %0, %1, %2;" : "=r"(r) : "f"(o), "f"(e)); return r;
}
__device__ __forceinline__ u16 f2bf(float v) {
    u16 u; asm("cvt.rn.bf16.f32 %0, %1;" : "=h"(u) : "f"(v)); return u;
}
__device__ __forceinline__ float bf2f(u16 u) { return __uint_as_float(((u32)u) << 16); }

__device__ __forceinline__ void ldsm4(u32& r0, u32& r1, u32& r2, u32& r3, u32 addr) {
    asm volatile("ldmatrix.sync.aligned.m8n8.x4.shared.b16 {%0,%1,%2,%3}, [%4];"
                 : "=r"(r0), "=r"(r1), "=r"(r2), "=r"(r3) : "r"(addr));
}
__device__ __forceinline__ void mma16816(float (&d)[4], u32 a0, u32 a1, u32 a2, u32 a3,
                                         u32 b0, u32 b1) {
    asm volatile("mma.sync.aligned.m16n8k16.row.col.f32.bf16.bf16.f32 "
                 "{%0,%1,%2,%3}, {%4,%5,%6,%7}, {%8,%9}, {%0,%1,%2,%3};"
                 : "+f"(d[0]), "+f"(d[1]), "+f"(d[2]), "+f"(d[3])
                 : "r"(a0), "r"(a1), "r"(a2), "r"(a3), "r"(b0), "r"(b1));
}
__device__ __forceinline__ void cp16(u32 dst, const void* src) {
    asm volatile("cp.async.cg.shared.global [%0], [%1], 16;" :: "r"(dst), "l"(src) : "memory");
}
#define CP_COMMIT() asm volatile("cp.async.commit_group;" ::: "memory")
#define CP_WAIT0()  asm volatile("cp.async.wait_group 0;" ::: "memory")

// ============================================================================
// Merge kernel: build L3/R2 and write hi/lo bf16 padded operand images.
// core0[a,1,i,v]: a*32+i*4+v      core1[b,i,j,w]: b*256+i*32+j*4+w
// core2[c,j,k,x]: c*512+j*64+k*8+x core3[d,k,l,y]: d*512+k*64+l*8+y
// core4[e,l,1,z]: e*32+l*4+z
// ============================================================================
__global__ __launch_bounds__(256)
void tt_merge_kernel(const float* __restrict__ c0, const float* __restrict__ c1,
                     const float* __restrict__ c2, const float* __restrict__ c3,
                     const float* __restrict__ c4)
{
    __shared__ float m12[2048];  // [ab][j][vw]
    const int tid = threadIdx.x;

    for (int idx = tid; idx < 2048; idx += blockDim.x) {
        int ab = idx >> 7, j = (idx >> 4) & 7, vw = idx & 15;
        int a = ab >> 2, b = ab & 3, v = vw >> 2, w = vw & 3;
        float s = 0.f;
#pragma unroll
        for (int i = 0; i < 8; ++i)
            s += c0[a * 32 + i * 4 + v] * c1[b * 256 + i * 32 + j * 4 + w];
        m12[idx] = s;
    }
    __syncthreads();

    const int stride = gridDim.x * blockDim.x;
    // L3: value (k, abc, vwx) -> image row=vwx, col=abc (272B padded rows)
    for (int idx = blockIdx.x * blockDim.x + tid; idx < 8 * 128 * 128; idx += stride) {
        int k = idx >> 14, abc = (idx >> 7) & 127, vwx = idx & 127;
        int ab = abc >> 3, c = abc & 7, vw = vwx >> 3, x = vwx & 7;
        float s = 0.f;
#pragma unroll
        for (int j = 0; j < 8; ++j)
            s += m12[ab * 128 + j * 16 + vw] * c2[c * 512 + j * 64 + k * 8 + x];
        u16 hi = f2bf(s);
        u16 lo = f2bf(s - bf2f(hi));
        g_L3pad[k][0][vwx * 136 + abc] = hi;
        g_L3pad[k][1][vwx * 136 + abc] = lo;
    }
    // R2: value (k, de, yz) -> image row=yz, col=de (80B padded rows)
    for (int idx = blockIdx.x * blockDim.x + tid; idx < 8 * 32 * 32; idx += stride) {
        int k = idx >> 10, yz = (idx >> 5) & 31, de = idx & 31;
        int d = de >> 2, e = de & 3, y = yz >> 2, z = yz & 3;
        float s = 0.f;
#pragma unroll
        for (int l = 0; l < 8; ++l)
            s += c3[d * 512 + k * 64 + l * 8 + y] * c4[e * 32 + l * 4 + z];
        u16 hi = f2bf(s);
        u16 lo = f2bf(s - bf2f(hi));
        g_R2pad[k][0][yz * 40 + de] = hi;
        g_R2pad[k][1][yz * 40 + de] = lo;
    }
}

// ============================================================================
// Fused mma kernel. 4 tokens per CTA, 256 threads (8 warps), 1 CTA/SM.
// SMEM: X images (hi+lo) 69632 | L3 slice (hi+lo, double-use scratch) 69632 |
//       R2 images (all k) 40960  = 180224 B
// ============================================================================
static constexpr int SM_X  = 0;
static constexpr int SM_L3 = 69632;
static constexpr int SM_R2 = 139264;
static constexpr int SMEM_BYTES = 180224;

__global__ __launch_bounds__(256, 1)
void tt_mma_kernel(const float* __restrict__ x, const float* __restrict__ bias,
                   float* __restrict__ out, int n_tokens)
{
    extern __shared__ __align__(16) char smem[];
    const u32 sb = smem_u32(smem);
    const int tid = threadIdx.x, w = tid >> 5, lane = tid & 31;
    const int n0 = blockIdx.x * 4;

    // ---- 1) bulk-copy X rows into scratch (= L3 buffer area), coalesced ----
    {
        const float4* xg = reinterpret_cast<const float4*>(x) + (size_t)n0 * 1024;
        float4* scr = reinterpret_cast<float4*>(smem + SM_L3);
#pragma unroll
        for (int it = 0; it < 16; ++it) {
            int i = tid + it * 256;
            float4 v = make_float4(0.f, 0.f, 0.f, 0.f);
            if (n0 + (i >> 10) < n_tokens) v = xg[i];
            scr[i] = v;
        }
    }
    __syncthreads();

    // ---- 2) build X bf16 hi/lo images: row = t*32+de, col = abc, 272B rows ----
    {
        const int t = w >> 1, ab0 = (w & 1) * 64;
        const float* s = reinterpret_cast<const float*>(smem + SM_L3) + t * 4096 + lane;
        const int row = t * 32 + lane;
        char* xh = smem + SM_X + row * 272;
        char* xl = xh + 34816;
#pragma unroll 8
        for (int a2i = 0; a2i < 32; ++a2i) {
            int cc = ab0 + 2 * a2i;
            float f0 = s[cc * 32];        // X[row][cc]   = x[n0+t][cc*32+de]
            float f1 = s[cc * 32 + 32];   // X[row][cc+1]
            u32 hw = pack2bf(f0, f1);
            float h0 = __uint_as_float(hw << 16);
            float h1 = __uint_as_float(hw & 0xFFFF0000u);
            u32 lw = pack2bf(f0 - h0, f1 - h1);
            *reinterpret_cast<u32*>(xh + cc * 2) = hw;
            *reinterpret_cast<u32*>(xl + cc * 2) = lw;
        }
    }
    __syncthreads();   // scratch consumed; safe to overwrite with L3 k=0

    // ---- 3) async load: all R2 images + L3 slice k=0 ----
    {
        const char* gr = reinterpret_cast<const char*>(&g_R2pad[0][0][0]);
#pragma unroll
        for (int it = 0; it < 10; ++it) { int i = tid + it * 256; cp16(sb + SM_R2 + i * 16, gr + i * 16); }
        const char* gl = reinterpret_cast<const char*>(&g_L3pad[0][0][0]);
#pragma unroll
        for (int it = 0; it < 17; ++it) { int i = tid + it * 256; cp16(sb + SM_L3 + i * 16, gl + i * 16); }
        CP_COMMIT();
    }

    // ---- per-lane ldmatrix address offsets ----
    const u32 a_lane = (u32)((((lane & 7) | (lane & 8)) * 272) + ((lane & 16) ? 16 : 0));
    const u32 b_lane = (u32)((((lane & 7) + ((lane & 16) ? 8 : 0)) * 272) + ((lane & 8) ? 16 : 0));
    const u32 r_lane = (u32)((((lane & 7) + ((lane & 16) ? 8 : 0)) * 80)  + ((lane & 8) ? 16 : 0));
    const u32 aw    = sb + SM_L3 + (u32)(w * 16 * 272) + a_lane;
    const u32 bbase = sb + SM_X + b_lane;
    const u32 rbase = sb + SM_R2 + r_lane;

    float d2[4][4][4];   // [token][yz n-tile][c-frag]
#pragma unroll
    for (int t = 0; t < 4; ++t)
#pragma unroll
        for (int jn = 0; jn < 4; ++jn)
#pragma unroll
            for (int q = 0; q < 4; ++q) d2[t][jn][q] = 0.f;

#pragma unroll 1
    for (int k = 0; k < 8; ++k) {
        CP_WAIT0();
        __syncthreads();   // L3 slice k resident

        // ---- stage 1: D1'[vwx 16-row strip][tde 128] = sum_abc L3^T . X ----
        float acc[16][4];
#pragma unroll
        for (int n = 0; n < 16; ++n)
#pragma unroll
            for (int q = 0; q < 4; ++q) acc[n][q] = 0.f;

#pragma unroll 1
        for (int p = 0; p < 3; ++p) {   // (Ah,Bh), (Ah,Bl), (Al,Bh)
            const u32 ab = aw    + ((p == 2) ? 34816u : 0u);
            const u32 bb = bbase + ((p == 1) ? 34816u : 0u);
#pragma unroll 1
            for (int kk = 0; kk < 8; ++kk) {
                u32 a0, a1, a2r, a3;
                ldsm4(a0, a1, a2r, a3, ab + kk * 32);
#pragma unroll
                for (int j = 0; j < 8; ++j) {
                    u32 r0, r1, r2, r3;
                    ldsm4(r0, r1, r2, r3, bb + j * 4352 + kk * 32);
                    mma16816(acc[2 * j],     a0, a1, a2r, a3, r0, r1);
                    mma16816(acc[2 * j + 1], a0, a1, a2r, a3, r2, r3);
                }
            }
        }
        __syncthreads();   // all warps done reading L3 slice k

        // ---- prefetch L3 slice k+1 (overlaps with stage 2) ----
        if (k < 7) {
            const char* gl = reinterpret_cast<const char*>(&g_L3pad[k + 1][0][0]);
#pragma unroll
            for (int it = 0; it < 17; ++it) { int i = tid + it * 256; cp16(sb + SM_L3 + i * 16, gl + i * 16); }
            CP_COMMIT();
        }

        // ---- stage 2: D2[vwx][yz] += D1'[vwx][de] . R2k^T, per token ----
        const u32 rk = rbase + (u32)(k * 5120);
#pragma unroll
        for (int p = 0; p < 3; ++p) {
            const u32 rb = rk + ((p == 1) ? 2560u : 0u);   // B img: lo only for p1
            u32 b2[4][2][2];
#pragma unroll
            for (int i = 0; i < 2; ++i)
#pragma unroll
                for (int kk = 0; kk < 2; ++kk) {
                    u32 r0, r1, r2, r3;
                    ldsm4(r0, r1, r2, r3, rb + i * 1280 + kk * 32);
                    b2[2 * i][kk][0] = r0; b2[2 * i][kk][1] = r1;
                    b2[2 * i + 1][kk][0] = r2; b2[2 * i + 1][kk][1] = r3;
                }
#pragma unroll
            for (int t = 0; t < 4; ++t) {
                // build A2 frags (hi for p0/p1, lo for p2) from stage-1 accumulators
                u32 a2[2][4];
#pragma unroll
                for (int kk = 0; kk < 2; ++kk) {
                    const float* cA = acc[4 * t + 2 * kk];
                    const float* cB = acc[4 * t + 2 * kk + 1];
                    u32 h0 = pack2bf(cA[0], cA[1]);
                    u32 h1 = pack2bf(cA[2], cA[3]);
                    u32 h2 = pack2bf(cB[0], cB[1]);
                    u32 h3 = pack2bf(cB[2], cB[3]);
                    if (p < 2) {
                        a2[kk][0] = h0; a2[kk][1] = h1; a2[kk][2] = h2; a2[kk][3] = h3;
                    } else {
                        a2[kk][0] = pack2bf(cA[0] - __uint_as_float(h0 << 16),
                                            cA[1] - __uint_as_float(h0 & 0xFFFF0000u));
                        a2[kk][1] = pack2bf(cA[2] - __uint_as_float(h1 << 16),
                                            cA[3] - __uint_as_float(h1 & 0xFFFF0000u));
                        a2[kk][2] = pack2bf(cB[0] - __uint_as_float(h2 << 16),
                                            cB[1] - __uint_as_float(h2 & 0xFFFF0000u));
                        a2[kk][3] = pack2bf(cB[2] - __uint_as_float(h3 << 16),
                                            cB[3] - __uint_as_float(h3 & 0xFFFF0000u));
                    }
                }
#pragma unroll
                for (int kk = 0; kk < 2; ++kk)
#pragma unroll
                    for (int jn = 0; jn < 4; ++jn)
                        mma16816(d2[t][jn], a2[kk][0], a2[kk][1], a2[kk][2], a2[kk][3],
                                 b2[jn][kk][0], b2[jn][kk][1]);
            }
        }
    }

    // ---- epilogue: bias + store. c-frag: rows vwx0, vwx0+8; cols 8*jn+2*tg ----
    const int g = lane >> 2, tg = lane & 3;
    const int vwx0 = 16 * w + g;
    float2 bv0[4], bv1[4];
#pragma unroll
    for (int jn = 0; jn < 4; ++jn) {
        bv0[jn] = *reinterpret_cast<const float2*>(bias + vwx0 * 32 + 8 * jn + 2 * tg);
        bv1[jn] = *reinterpret_cast<const float2*>(bias + (vwx0 + 8) * 32 + 8 * jn + 2 * tg);
    }
#pragma unroll
    for (int t = 0; t < 4; ++t) {
        if (n0 + t < n_tokens) {
            float* o = out + (size_t)(n0 + t) * 4096;
#pragma unroll
            for (int jn = 0; jn < 4; ++jn) {
                float2 v0 = make_float2(d2[t][jn][0] + bv0[jn].x, d2[t][jn][1] + bv0[jn].y);
                float2 v1 = make_float2(d2[t][jn][2] + bv1[jn].x, d2[t][jn][3] + bv1[jn].y);
                *reinterpret_cast<float2*>(o + vwx0 * 32 + 8 * jn + 2 * tg) = v0;
                *reinterpret_cast<float2*>(o + (vwx0 + 8) * 32 + 8 * jn + 2 * tg) = v1;
            }
        }
    }
}

// ============================================================================
// Launch. Inputs: input, core0..core4, biases. Output fp32 [n, 4096].
// ============================================================================
extern "C" void kernel_launch(void* const* d_in, const int* in_sizes, int n_in,
                              void* d_out, int out_size)
{
    const float* x    = (const float*)d_in[0];
    const float* c0   = (const float*)d_in[1];
    const float* c1   = (const float*)d_in[2];
    const float* c2   = (const float*)d_in[3];
    const float* c3   = (const float*)d_in[4];
    const float* c4   = (const float*)d_in[5];
    const float* bias = (const float*)d_in[6];
    float* out = (float*)d_out;

    const int n_tokens = in_sizes[0] / 4096;

    cudaFuncSetAttribute(tt_mma_kernel,
                         cudaFuncAttributeMaxDynamicSharedMemorySize, SMEM_BYTES);

    tt_merge_kernel<<<32, 256>>>(c0, c1, c2, c3, c4);

    const int grid = (n_tokens + 3) / 4;
    tt_mma_kernel<<<grid, 256, SMEM_BYTES>>>(x, bias, out, n_tokens);
}

// round 13
// speedup vs baseline: 1.0013x; 1.0013x over previous
#include <cuda_runtime.h>
#include <cuda_bf16.h>

typedef unsigned int       u32;
typedef unsigned short     u16;
typedef unsigned long long u64;

// ============================================================================
// TT linear via mma.sync (bf16 hi/lo split, 3-product fp32 emulation).
//   L3[k][abc][vwx] = G1*G2*G3 ;  R2[k][de][yz] = G4*G5
//   stage1 (per k): D1'[vwx][(t,de)] = L3k^T[vwx][abc] . X[(t,de)][abc]
//   stage2 (acc k): D2[vwx][t*? yz]  += D1'[vwx][de]   . R2k^T[yz][de]
// Intermediate D1' stays in registers; A2 fragments built with bf16x2 packs.
// ============================================================================

// Padded global operand images (row strides chosen for conflict-free ldmatrix)
__device__ __align__(16) u16 g_L3pad[8][2][17408]; // [k][hi/lo][vwx*136 + abc], 272B rows
__device__ __align__(16) u16 g_R2pad[8][2][1280];  // [k][hi/lo][yz*40 + de],   80B rows

// ---------------- helpers ----------------
__device__ __forceinline__ u32 smem_u32(const void* p) {
    u32 a; asm("{ .reg .u64 t; cvta.to.shared.u64 t, %1; cvt.u32.u64 %0, t; }" : "=r"(a) : "l"(p));
    return a;
}
// pack: low half <- e (first elem), high half <- o (second elem)
__device__ __forceinline__ u32 pack2bf(float e, float o) {
    u32 r; asm("cvt.rn.bf16x2.f32 %0, %1, %2;" : "=r"(r) : "f"(o), "f"(e)); return r;
}
__device__ __forceinline__ u16 f2bf(float v) {
    u16 u; asm("cvt.rn.bf16.f32 %0, %1;" : "=h"(u) : "f"(v)); return u;
}
__device__ __forceinline__ float bf2f(u16 u) { return __uint_as_float(((u32)u) << 16); }

__device__ __forceinline__ void ldsm4(u32& r0, u32& r1, u32& r2, u32& r3, u32 addr) {
    asm volatile("ldmatrix.sync.aligned.m8n8.x4.shared.b16 {%0,%1,%2,%3}, [%4];"
                 : "=r"(r0), "=r"(r1), "=r"(r2), "=r"(r3) : "r"(addr));
}
__device__ __forceinline__ void mma16816(float (&d)[4], u32 a0, u32 a1, u32 a2, u32 a3,
                                         u32 b0, u32 b1) {
    asm volatile("mma.sync.aligned.m16n8k16.row.col.f32.bf16.bf16.f32 "
                 "{%0,%1,%2,%3}, {%4,%5,%6,%7}, {%8,%9}, {%0,%1,%2,%3};"
                 : "+f"(d[0]), "+f"(d[1]), "+f"(d[2]), "+f"(d[3])
                 : "r"(a0), "r"(a1), "r"(a2), "r"(a3), "r"(b0), "r"(b1));
}
__device__ __forceinline__ void cp16(u32 dst, const void* src) {
    asm volatile("cp.async.cg.shared.global [%0], [%1], 16;" :: "r"(dst), "l"(src) : "memory");
}
#define CP_COMMIT() asm volatile("cp.async.commit_group;" ::: "memory")
#define CP_WAIT0()  asm volatile("cp.async.wait_group 0;" ::: "memory")

// ============================================================================
// Merge kernel: build L3/R2 and write hi/lo bf16 padded operand images.
// core0[a,1,i,v]: a*32+i*4+v      core1[b,i,j,w]: b*256+i*32+j*4+w
// core2[c,j,k,x]: c*512+j*64+k*8+x core3[d,k,l,y]: d*512+k*64+l*8+y
// core4[e,l,1,z]: e*32+l*4+z
// ============================================================================
__global__ __launch_bounds__(256)
void tt_merge_kernel(const float* __restrict__ c0, const float* __restrict__ c1,
                     const float* __restrict__ c2, const float* __restrict__ c3,
                     const float* __restrict__ c4)
{
    __shared__ float m12[2048];  // [ab][j][vw]
    const int tid = threadIdx.x;

    for (int idx = tid; idx < 2048; idx += blockDim.x) {
        int ab = idx >> 7, j = (idx >> 4) & 7, vw = idx & 15;
        int a = ab >> 2, b = ab & 3, v = vw >> 2, w = vw & 3;
        float s = 0.f;
#pragma unroll
        for (int i = 0; i < 8; ++i)
            s += c0[a * 32 + i * 4 + v] * c1[b * 256 + i * 32 + j * 4 + w];
        m12[idx] = s;
    }
    __syncthreads();

    const int stride = gridDim.x * blockDim.x;
    // L3: value (k, abc, vwx) -> image row=vwx, col=abc (272B padded rows)
    for (int idx = blockIdx.x * blockDim.x + tid; idx < 8 * 128 * 128; idx += stride) {
        int k = idx >> 14, abc = (idx >> 7) & 127, vwx = idx & 127;
        int ab = abc >> 3, c = abc & 7, vw = vwx >> 3, x = vwx & 7;
        float s = 0.f;
#pragma unroll
        for (int j = 0; j < 8; ++j)
            s += m12[ab * 128 + j * 16 + vw] * c2[c * 512 + j * 64 + k * 8 + x];
        u16 hi = f2bf(s);
        u16 lo = f2bf(s - bf2f(hi));
        g_L3pad[k][0][vwx * 136 + abc] = hi;
        g_L3pad[k][1][vwx * 136 + abc] = lo;
    }
    // R2: value (k, de, yz) -> image row=yz, col=de (80B padded rows)
    for (int idx = blockIdx.x * blockDim.x + tid; idx < 8 * 32 * 32; idx += stride) {
        int k = idx >> 10, yz = (idx >> 5) & 31, de = idx & 31;
        int d = de >> 2, e = de & 3, y = yz >> 2, z = yz & 3;
        float s = 0.f;
#pragma unroll
        for (int l = 0; l < 8; ++l)
            s += c3[d * 512 + k * 64 + l * 8 + y] * c4[e * 32 + l * 4 + z];
        u16 hi = f2bf(s);
        u16 lo = f2bf(s - bf2f(hi));
        g_R2pad[k][0][yz * 40 + de] = hi;
        g_R2pad[k][1][yz * 40 + de] = lo;
    }
}

// ============================================================================
// Fused mma kernel. 4 tokens per CTA, 256 threads (8 warps), 1 CTA/SM.
// SMEM: X images (hi+lo) 69632 | L3 slice (hi+lo, double-use scratch) 69632 |
//       R2 images (all k) 40960  = 180224 B
// ============================================================================
static constexpr int SM_X  = 0;
static constexpr int SM_L3 = 69632;
static constexpr int SM_R2 = 139264;
static constexpr int SMEM_BYTES = 180224;

__global__ __launch_bounds__(256, 1)
void tt_mma_kernel(const float* __restrict__ x, const float* __restrict__ bias,
                   float* __restrict__ out, int n_tokens)
{
    extern __shared__ __align__(16) char smem[];
    const u32 sb = smem_u32(smem);
    const int tid = threadIdx.x, w = tid >> 5, lane = tid & 31;
    const int n0 = blockIdx.x * 4;

    // ---- 1) bulk-copy X rows into scratch (= L3 buffer area), coalesced ----
    {
        const float4* xg = reinterpret_cast<const float4*>(x) + (size_t)n0 * 1024;
        float4* scr = reinterpret_cast<float4*>(smem + SM_L3);
#pragma unroll
        for (int it = 0; it < 16; ++it) {
            int i = tid + it * 256;
            float4 v = make_float4(0.f, 0.f, 0.f, 0.f);
            if (n0 + (i >> 10) < n_tokens) v = xg[i];
            scr[i] = v;
        }
    }
    __syncthreads();

    // ---- 2) build X bf16 hi/lo images: row = t*32+de, col = abc, 272B rows ----
    {
        const int t = w >> 1, ab0 = (w & 1) * 64;
        const float* s = reinterpret_cast<const float*>(smem + SM_L3) + t * 4096 + lane;
        const int row = t * 32 + lane;
        char* xh = smem + SM_X + row * 272;
        char* xl = xh + 34816;
#pragma unroll 8
        for (int a2i = 0; a2i < 32; ++a2i) {
            int cc = ab0 + 2 * a2i;
            float f0 = s[cc * 32];        // X[row][cc]   = x[n0+t][cc*32+de]
            float f1 = s[cc * 32 + 32];   // X[row][cc+1]
            u32 hw = pack2bf(f0, f1);
            float h0 = __uint_as_float(hw << 16);
            float h1 = __uint_as_float(hw & 0xFFFF0000u);
            u32 lw = pack2bf(f0 - h0, f1 - h1);
            *reinterpret_cast<u32*>(xh + cc * 2) = hw;
            *reinterpret_cast<u32*>(xl + cc * 2) = lw;
        }
    }
    __syncthreads();   // scratch consumed; safe to overwrite with L3 k=0

    // ---- 3) async load: all R2 images + L3 slice k=0 ----
    {
        const char* gr = reinterpret_cast<const char*>(&g_R2pad[0][0][0]);
#pragma unroll
        for (int it = 0; it < 10; ++it) { int i = tid + it * 256; cp16(sb + SM_R2 + i * 16, gr + i * 16); }
        const char* gl = reinterpret_cast<const char*>(&g_L3pad[0][0][0]);
#pragma unroll
        for (int it = 0; it < 17; ++it) { int i = tid + it * 256; cp16(sb + SM_L3 + i * 16, gl + i * 16); }
        CP_COMMIT();
    }

    // ---- per-lane ldmatrix address offsets ----
    const u32 a_lane = (u32)((((lane & 7) | (lane & 8)) * 272) + ((lane & 16) ? 16 : 0));
    const u32 b_lane = (u32)((((lane & 7) + ((lane & 16) ? 8 : 0)) * 272) + ((lane & 8) ? 16 : 0));
    const u32 r_lane = (u32)((((lane & 7) + ((lane & 16) ? 8 : 0)) * 80)  + ((lane & 8) ? 16 : 0));
    const u32 aw    = sb + SM_L3 + (u32)(w * 16 * 272) + a_lane;
    const u32 bbase = sb + SM_X + b_lane;
    const u32 rbase = sb + SM_R2 + r_lane;

    float d2[4][4][4];   // [token][yz n-tile][c-frag]
#pragma unroll
    for (int t = 0; t < 4; ++t)
#pragma unroll
        for (int jn = 0; jn < 4; ++jn)
#pragma unroll
            for (int q = 0; q < 4; ++q) d2[t][jn][q] = 0.f;

#pragma unroll 1
    for (int k = 0; k < 8; ++k) {
        CP_WAIT0();
        __syncthreads();   // L3 slice k resident

        // ---- stage 1: D1'[vwx 16-row strip][tde 128] = sum_abc L3^T . X ----
        float acc[16][4];
#pragma unroll
        for (int n = 0; n < 16; ++n)
#pragma unroll
            for (int q = 0; q < 4; ++q) acc[n][q] = 0.f;

#pragma unroll 1
        for (int p = 0; p < 3; ++p) {   // (Ah,Bh), (Ah,Bl), (Al,Bh)
            const u32 ab = aw    + ((p == 2) ? 34816u : 0u);
            const u32 bb = bbase + ((p == 1) ? 34816u : 0u);
#pragma unroll 1
            for (int kk = 0; kk < 8; ++kk) {
                u32 a0, a1, a2r, a3;
                ldsm4(a0, a1, a2r, a3, ab + kk * 32);
#pragma unroll
                for (int j = 0; j < 8; ++j) {
                    u32 r0, r1, r2, r3;
                    ldsm4(r0, r1, r2, r3, bb + j * 4352 + kk * 32);
                    mma16816(acc[2 * j],     a0, a1, a2r, a3, r0, r1);
                    mma16816(acc[2 * j + 1], a0, a1, a2r, a3, r2, r3);
                }
            }
        }
        __syncthreads();   // all warps done reading L3 slice k

        // ---- prefetch L3 slice k+1 (overlaps with stage 2) ----
        if (k < 7) {
            const char* gl = reinterpret_cast<const char*>(&g_L3pad[k + 1][0][0]);
#pragma unroll
            for (int it = 0; it < 17; ++it) { int i = tid + it * 256; cp16(sb + SM_L3 + i * 16, gl + i * 16); }
            CP_COMMIT();
        }

        // ---- stage 2: D2[vwx][yz] += D1'[vwx][de] . R2k^T, per token ----
        const u32 rk = rbase + (u32)(k * 5120);
#pragma unroll
        for (int p = 0; p < 3; ++p) {
            const u32 rb = rk + ((p == 1) ? 2560u : 0u);   // B img: lo only for p1
            u32 b2[4][2][2];
#pragma unroll
            for (int i = 0; i < 2; ++i)
#pragma unroll
                for (int kk = 0; kk < 2; ++kk) {
                    u32 r0, r1, r2, r3;
                    ldsm4(r0, r1, r2, r3, rb + i * 1280 + kk * 32);
                    b2[2 * i][kk][0] = r0; b2[2 * i][kk][1] = r1;
                    b2[2 * i + 1][kk][0] = r2; b2[2 * i + 1][kk][1] = r3;
                }
#pragma unroll
            for (int t = 0; t < 4; ++t) {
                // build A2 frags (hi for p0/p1, lo for p2) from stage-1 accumulators
                u32 a2[2][4];
#pragma unroll
                for (int kk = 0; kk < 2; ++kk) {
                    const float* cA = acc[4 * t + 2 * kk];
                    const float* cB = acc[4 * t + 2 * kk + 1];
                    u32 h0 = pack2bf(cA[0], cA[1]);
                    u32 h1 = pack2bf(cA[2], cA[3]);
                    u32 h2 = pack2bf(cB[0], cB[1]);
                    u32 h3 = pack2bf(cB[2], cB[3]);
                    if (p < 2) {
                        a2[kk][0] = h0; a2[kk][1] = h1; a2[kk][2] = h2; a2[kk][3] = h3;
                    } else {
                        a2[kk][0] = pack2bf(cA[0] - __uint_as_float(h0 << 16),
                                            cA[1] - __uint_as_float(h0 & 0xFFFF0000u));
                        a2[kk][1] = pack2bf(cA[2] - __uint_as_float(h1 << 16),
                                            cA[3] - __uint_as_float(h1 & 0xFFFF0000u));
                        a2[kk][2] = pack2bf(cB[0] - __uint_as_float(h2 << 16),
                                            cB[1] - __uint_as_float(h2 & 0xFFFF0000u));
                        a2[kk][3] = pack2bf(cB[2] - __uint_as_float(h3 << 16),
                                            cB[3] - __uint_as_float(h3 & 0xFFFF0000u));
                    }
                }
#pragma unroll
                for (int kk = 0; kk < 2; ++kk)
#pragma unroll
                    for (int jn = 0; jn < 4; ++jn)
                        mma16816(d2[t][jn], a2[kk][0], a2[kk][1], a2[kk][2], a2[kk][3],
                                 b2[jn][kk][0], b2[jn][kk][1]);
            }
        }
    }

    // ---- epilogue: bias + store. c-frag: rows vwx0, vwx0+8; cols 8*jn+2*tg ----
    const int g = lane >> 2, tg = lane & 3;
    const int vwx0 = 16 * w + g;
    float2 bv0[4], bv1[4];
#pragma unroll
    for (int jn = 0; jn < 4; ++jn) {
        bv0[jn] = *reinterpret_cast<const float2*>(bias + vwx0 * 32 + 8 * jn + 2 * tg);
        bv1[jn] = *reinterpret_cast<const float2*>(bias + (vwx0 + 8) * 32 + 8 * jn + 2 * tg);
    }
#pragma unroll
    for (int t = 0; t < 4; ++t) {
        if (n0 + t < n_tokens) {
            float* o = out + (size_t)(n0 + t) * 4096;
#pragma unroll
            for (int jn = 0; jn < 4; ++jn) {
                float2 v0 = make_float2(d2[t][jn][0] + bv0[jn].x, d2[t][jn][1] + bv0[jn].y);
                float2 v1 = make_float2(d2[t][jn][2] + bv1[jn].x, d2[t][jn][3] + bv1[jn].y);
                *reinterpret_cast<float2*>(o + vwx0 * 32 + 8 * jn + 2 * tg) = v0;
                *reinterpret_cast<float2*>(o + (vwx0 + 8) * 32 + 8 * jn + 2 * tg) = v1;
            }
        }
    }
}

// ============================================================================
// Launch. Inputs: input, core0..core4, biases. Output fp32 [n, 4096].
// ============================================================================
extern "C" void kernel_launch(void* const* d_in, const int* in_sizes, int n_in,
                              void* d_out, int out_size)
{
    const float* x    = (const float*)d_in[0];
    const float* c0   = (const float*)d_in[1];
    const float* c1   = (const float*)d_in[2];
    const float* c2   = (const float*)d_in[3];
    const float* c3   = (const float*)d_in[4];
    const float* c4   = (const float*)d_in[5];
    const float* bias = (const float*)d_in[6];
    float* out = (float*)d_out;

    const int n_tokens = in_sizes[0] / 4096;

    cudaFuncSetAttribute(tt_mma_kernel,
                         cudaFuncAttributeMaxDynamicSharedMemorySize, SMEM_BYTES);

    tt_merge_kernel<<<32, 256>>>(c0, c1, c2, c3, c4);

    const int grid = (n_tokens + 3) / 4;
    tt_mma_kernel<<<grid, 256, SMEM_BYTES>>>(x, bias, out, n_tokens);
}

// round 14
// speedup vs baseline: 1.0038x; 1.0026x over previous
#include <cuda_runtime.h>
#include <cuda_bf16.h>

typedef unsigned int       u32;
typedef unsigned short     u16;
typedef unsigned long long u64;

// ============================================================================
// TT linear via mma.sync (bf16 hi/lo split, 3-product fp32 emulation).
//   L3[k][abc][vwx] = G1*G2*G3 ;  R2[k][de][yz] = G4*G5
//   stage1 (per k): D1'[vwx][(t,de)] = L3k^T[vwx][abc] . X[(t,de)][abc]
//   stage2 (acc k): D2[vwx][t*? yz]  += D1'[vwx][de]   . R2k^T[yz][de]
// Intermediate D1' stays in registers; A2 fragments built with bf16x2 packs.
// ============================================================================

// Padded global operand images (row strides chosen for conflict-free ldmatrix)
__device__ __align__(16) u16 g_L3pad[8][2][17408]; // [k][hi/lo][vwx*136 + abc], 272B rows
__device__ __align__(16) u16 g_R2pad[8][2][1280];  // [k][hi/lo][yz*40 + de],   80B rows

// ---------------- helpers ----------------
__device__ __forceinline__ u32 smem_u32(const void* p) {
    u32 a; asm("{ .reg .u64 t; cvta.to.shared.u64 t, %1; cvt.u32.u64 %0, t; }" : "=r"(a) : "l"(p));
    return a;
}
// pack: low half <- e (first elem), high half <- o (second elem)
__device__ __forceinline__ u32 pack2bf(float e, float o) {
    u32 r; asm("cvt.rn.bf16x2.f32 %0, %1, %2;" : "=r"(r) : "f"(o), "f"(e)); return r;
}
__device__ __forceinline__ u16 f2bf(float v) {
    u16 u; asm("cvt.rn.bf16.f32 %0, %1;" : "=h"(u) : "f"(v)); return u;
}
__device__ __forceinline__ float bf2f(u16 u) { return __uint_as_float(((u32)u) << 16); }

__device__ __forceinline__ void ldsm4(u32& r0, u32& r1, u32& r2, u32& r3, u32 addr) {
    asm volatile("ldmatrix.sync.aligned.m8n8.x4.shared.b16 {%0,%1,%2,%3}, [%4];"
                 : "=r"(r0), "=r"(r1), "=r"(r2), "=r"(r3) : "r"(addr));
}
__device__ __forceinline__ void mma16816(float (&d)[4], u32 a0, u32 a1, u32 a2, u32 a3,
                                         u32 b0, u32 b1) {
    asm volatile("mma.sync.aligned.m16n8k16.row.col.f32.bf16.bf16.f32 "
                 "{%0,%1,%2,%3}, {%4,%5,%6,%7}, {%8,%9}, {%0,%1,%2,%3};"
                 : "+f"(d[0]), "+f"(d[1]), "+f"(d[2]), "+f"(d[3])
                 : "r"(a0), "r"(a1), "r"(a2), "r"(a3), "r"(b0), "r"(b1));
}
__device__ __forceinline__ void cp16(u32 dst, const void* src) {
    asm volatile("cp.async.cg.shared.global [%0], [%1], 16;" :: "r"(dst), "l"(src) : "memory");
}
#define CP_COMMIT() asm volatile("cp.async.commit_group;" ::: "memory")
#define CP_WAIT0()  asm volatile("cp.async.wait_group 0;" ::: "memory")

// ============================================================================
// Merge kernel: build L3/R2 and write hi/lo bf16 padded operand images.
// core0[a,1,i,v]: a*32+i*4+v      core1[b,i,j,w]: b*256+i*32+j*4+w
// core2[c,j,k,x]: c*512+j*64+k*8+x core3[d,k,l,y]: d*512+k*64+l*8+y
// core4[e,l,1,z]: e*32+l*4+z
// ============================================================================
__global__ __launch_bounds__(256)
void tt_merge_kernel(const float* __restrict__ c0, const float* __restrict__ c1,
                     const float* __restrict__ c2, const float* __restrict__ c3,
                     const float* __restrict__ c4)
{
    __shared__ float m12[2048];  // [ab][j][vw]
    const int tid = threadIdx.x;

    for (int idx = tid; idx < 2048; idx += blockDim.x) {
        int ab = idx >> 7, j = (idx >> 4) & 7, vw = idx & 15;
        int a = ab >> 2, b = ab & 3, v = vw >> 2, w = vw & 3;
        float s = 0.f;
#pragma unroll
        for (int i = 0; i < 8; ++i)
            s += c0[a * 32 + i * 4 + v] * c1[b * 256 + i * 32 + j * 4 + w];
        m12[idx] = s;
    }
    __syncthreads();

    const int stride = gridDim.x * blockDim.x;
    // L3: value (k, abc, vwx) -> image row=vwx, col=abc (272B padded rows)
    for (int idx = blockIdx.x * blockDim.x + tid; idx < 8 * 128 * 128; idx += stride) {
        int k = idx >> 14, abc = (idx >> 7) & 127, vwx = idx & 127;
        int ab = abc >> 3, c = abc & 7, vw = vwx >> 3, x = vwx & 7;
        float s = 0.f;
#pragma unroll
        for (int j = 0; j < 8; ++j)
            s += m12[ab * 128 + j * 16 + vw] * c2[c * 512 + j * 64 + k * 8 + x];
        u16 hi = f2bf(s);
        u16 lo = f2bf(s - bf2f(hi));
        g_L3pad[k][0][vwx * 136 + abc] = hi;
        g_L3pad[k][1][vwx * 136 + abc] = lo;
    }
    // R2: value (k, de, yz) -> image row=yz, col=de (80B padded rows)
    for (int idx = blockIdx.x * blockDim.x + tid; idx < 8 * 32 * 32; idx += stride) {
        int k = idx >> 10, yz = (idx >> 5) & 31, de = idx & 31;
        int d = de >> 2, e = de & 3, y = yz >> 2, z = yz & 3;
        float s = 0.f;
#pragma unroll
        for (int l = 0; l < 8; ++l)
            s += c3[d * 512 + k * 64 + l * 8 + y] * c4[e * 32 + l * 4 + z];
        u16 hi = f2bf(s);
        u16 lo = f2bf(s - bf2f(hi));
        g_R2pad[k][0][yz * 40 + de] = hi;
        g_R2pad[k][1][yz * 40 + de] = lo;
    }
}

// ============================================================================
// Fused mma kernel. 4 tokens per CTA, 256 threads (8 warps), 1 CTA/SM.
// SMEM: X images (hi+lo) 69632 | L3 slice (hi+lo, double-use scratch) 69632 |
//       R2 images (all k) 40960  = 180224 B
// ============================================================================
static constexpr int SM_X  = 0;
static constexpr int SM_L3 = 69632;
static constexpr int SM_R2 = 139264;
static constexpr int SMEM_BYTES = 180224;

__global__ __launch_bounds__(256, 1)
void tt_mma_kernel(const float* __restrict__ x, const float* __restrict__ bias,
                   float* __restrict__ out, int n_tokens)
{
    extern __shared__ __align__(16) char smem[];
    const u32 sb = smem_u32(smem);
    const int tid = threadIdx.x, w = tid >> 5, lane = tid & 31;
    const int n0 = blockIdx.x * 4;

    // ---- 1) bulk-copy X rows into scratch (= L3 buffer area), coalesced ----
    {
        const float4* xg = reinterpret_cast<const float4*>(x) + (size_t)n0 * 1024;
        float4* scr = reinterpret_cast<float4*>(smem + SM_L3);
#pragma unroll
        for (int it = 0; it < 16; ++it) {
            int i = tid + it * 256;
            float4 v = make_float4(0.f, 0.f, 0.f, 0.f);
            if (n0 + (i >> 10) < n_tokens) v = xg[i];
            scr[i] = v;
        }
    }
    __syncthreads();

    // ---- 2) build X bf16 hi/lo images: row = t*32+de, col = abc, 272B rows ----
    {
        const int t = w >> 1, ab0 = (w & 1) * 64;
        const float* s = reinterpret_cast<const float*>(smem + SM_L3) + t * 4096 + lane;
        const int row = t * 32 + lane;
        char* xh = smem + SM_X + row * 272;
        char* xl = xh + 34816;
#pragma unroll 8
        for (int a2i = 0; a2i < 32; ++a2i) {
            int cc = ab0 + 2 * a2i;
            float f0 = s[cc * 32];        // X[row][cc]   = x[n0+t][cc*32+de]
            float f1 = s[cc * 32 + 32];   // X[row][cc+1]
            u32 hw = pack2bf(f0, f1);
            float h0 = __uint_as_float(hw << 16);
            float h1 = __uint_as_float(hw & 0xFFFF0000u);
            u32 lw = pack2bf(f0 - h0, f1 - h1);
            *reinterpret_cast<u32*>(xh + cc * 2) = hw;
            *reinterpret_cast<u32*>(xl + cc * 2) = lw;
        }
    }
    __syncthreads();   // scratch consumed; safe to overwrite with L3 k=0

    // ---- 3) async load: all R2 images + L3 slice k=0 ----
    {
        const char* gr = reinterpret_cast<const char*>(&g_R2pad[0][0][0]);
#pragma unroll
        for (int it = 0; it < 10; ++it) { int i = tid + it * 256; cp16(sb + SM_R2 + i * 16, gr + i * 16); }
        const char* gl = reinterpret_cast<const char*>(&g_L3pad[0][0][0]);
#pragma unroll
        for (int it = 0; it < 17; ++it) { int i = tid + it * 256; cp16(sb + SM_L3 + i * 16, gl + i * 16); }
        CP_COMMIT();
    }

    // ---- per-lane ldmatrix address offsets ----
    const u32 a_lane = (u32)((((lane & 7) | (lane & 8)) * 272) + ((lane & 16) ? 16 : 0));
    const u32 b_lane = (u32)((((lane & 7) + ((lane & 16) ? 8 : 0)) * 272) + ((lane & 8) ? 16 : 0));
    const u32 r_lane = (u32)((((lane & 7) + ((lane & 16) ? 8 : 0)) * 80)  + ((lane & 8) ? 16 : 0));
    const u32 aw    = sb + SM_L3 + (u32)(w * 16 * 272) + a_lane;
    const u32 bbase = sb + SM_X + b_lane;
    const u32 rbase = sb + SM_R2 + r_lane;

    float d2[4][4][4];   // [token][yz n-tile][c-frag]
#pragma unroll
    for (int t = 0; t < 4; ++t)
#pragma unroll
        for (int jn = 0; jn < 4; ++jn)
#pragma unroll
            for (int q = 0; q < 4; ++q) d2[t][jn][q] = 0.f;

#pragma unroll 1
    for (int k = 0; k < 8; ++k) {
        CP_WAIT0();
        __syncthreads();   // L3 slice k resident

        // ---- stage 1: D1'[vwx 16-row strip][tde 128] = sum_abc L3^T . X ----
        float acc[16][4];
#pragma unroll
        for (int n = 0; n < 16; ++n)
#pragma unroll
            for (int q = 0; q < 4; ++q) acc[n][q] = 0.f;

#pragma unroll 1
        for (int p = 0; p < 3; ++p) {   // (Ah,Bh), (Ah,Bl), (Al,Bh)
            const u32 ab = aw    + ((p == 2) ? 34816u : 0u);
            const u32 bb = bbase + ((p == 1) ? 34816u : 0u);
#pragma unroll 1
            for (int kk = 0; kk < 8; ++kk) {
                u32 a0, a1, a2r, a3;
                ldsm4(a0, a1, a2r, a3, ab + kk * 32);
#pragma unroll
                for (int j = 0; j < 8; ++j) {
                    u32 r0, r1, r2, r3;
                    ldsm4(r0, r1, r2, r3, bb + j * 4352 + kk * 32);
                    mma16816(acc[2 * j],     a0, a1, a2r, a3, r0, r1);
                    mma16816(acc[2 * j + 1], a0, a1, a2r, a3, r2, r3);
                }
            }
        }
        __syncthreads();   // all warps done reading L3 slice k

        // ---- prefetch L3 slice k+1 (overlaps with stage 2) ----
        if (k < 7) {
            const char* gl = reinterpret_cast<const char*>(&g_L3pad[k + 1][0][0]);
#pragma unroll
            for (int it = 0; it < 17; ++it) { int i = tid + it * 256; cp16(sb + SM_L3 + i * 16, gl + i * 16); }
            CP_COMMIT();
        }

        // ---- stage 2: D2[vwx][yz] += D1'[vwx][de] . R2k^T, per token ----
        const u32 rk = rbase + (u32)(k * 5120);
#pragma unroll
        for (int p = 0; p < 3; ++p) {
            const u32 rb = rk + ((p == 1) ? 2560u : 0u);   // B img: lo only for p1
            u32 b2[4][2][2];
#pragma unroll
            for (int i = 0; i < 2; ++i)
#pragma unroll
                for (int kk = 0; kk < 2; ++kk) {
                    u32 r0, r1, r2, r3;
                    ldsm4(r0, r1, r2, r3, rb + i * 1280 + kk * 32);
                    b2[2 * i][kk][0] = r0; b2[2 * i][kk][1] = r1;
                    b2[2 * i + 1][kk][0] = r2; b2[2 * i + 1][kk][1] = r3;
                }
#pragma unroll
            for (int t = 0; t < 4; ++t) {
                // build A2 frags (hi for p0/p1, lo for p2) from stage-1 accumulators
                u32 a2[2][4];
#pragma unroll
                for (int kk = 0; kk < 2; ++kk) {
                    const float* cA = acc[4 * t + 2 * kk];
                    const float* cB = acc[4 * t + 2 * kk + 1];
                    u32 h0 = pack2bf(cA[0], cA[1]);
                    u32 h1 = pack2bf(cA[2], cA[3]);
                    u32 h2 = pack2bf(cB[0], cB[1]);
                    u32 h3 = pack2bf(cB[2], cB[3]);
                    if (p < 2) {
                        a2[kk][0] = h0; a2[kk][1] = h1; a2[kk][2] = h2; a2[kk][3] = h3;
                    } else {
                        a2[kk][0] = pack2bf(cA[0] - __uint_as_float(h0 << 16),
                                            cA[1] - __uint_as_float(h0 & 0xFFFF0000u));
                        a2[kk][1] = pack2bf(cA[2] - __uint_as_float(h1 << 16),
                                            cA[3] - __uint_as_float(h1 & 0xFFFF0000u));
                        a2[kk][2] = pack2bf(cB[0] - __uint_as_float(h2 << 16),
                                            cB[1] - __uint_as_float(h2 & 0xFFFF0000u));
                        a2[kk][3] = pack2bf(cB[2] - __uint_as_float(h3 << 16),
                                            cB[3] - __uint_as_float(h3 & 0xFFFF0000u));
                    }
                }
#pragma unroll
                for (int kk = 0; kk < 2; ++kk)
#pragma unroll
                    for (int jn = 0; jn < 4; ++jn)
                        mma16816(d2[t][jn], a2[kk][0], a2[kk][1], a2[kk][2], a2[kk][3],
                                 b2[jn][kk][0], b2[jn][kk][1]);
            }
        }
    }

    // ---- epilogue: bias + store. c-frag: rows vwx0, vwx0+8; cols 8*jn+2*tg ----
    const int g = lane >> 2, tg = lane & 3;
    const int vwx0 = 16 * w + g;
    float2 bv0[4], bv1[4];
#pragma unroll
    for (int jn = 0; jn < 4; ++jn) {
        bv0[jn] = *reinterpret_cast<const float2*>(bias + vwx0 * 32 + 8 * jn + 2 * tg);
        bv1[jn] = *reinterpret_cast<const float2*>(bias + (vwx0 + 8) * 32 + 8 * jn + 2 * tg);
    }
#pragma unroll
    for (int t = 0; t < 4; ++t) {
        if (n0 + t < n_tokens) {
            float* o = out + (size_t)(n0 + t) * 4096;
#pragma unroll
            for (int jn = 0; jn < 4; ++jn) {
                float2 v0 = make_float2(d2[t][jn][0] + bv0[jn].x, d2[t][jn][1] + bv0[jn].y);
                float2 v1 = make_float2(d2[t][jn][2] + bv1[jn].x, d2[t][jn][3] + bv1[jn].y);
                *reinterpret_cast<float2*>(o + vwx0 * 32 + 8 * jn + 2 * tg) = v0;
                *reinterpret_cast<float2*>(o + (vwx0 + 8) * 32 + 8 * jn + 2 * tg) = v1;
            }
        }
    }
}

// ============================================================================
// Launch. Inputs: input, core0..core4, biases. Output fp32 [n, 4096].
// ============================================================================
extern "C" void kernel_launch(void* const* d_in, const int* in_sizes, int n_in,
                              void* d_out, int out_size)
{
    const float* x    = (const float*)d_in[0];
    const float* c0   = (const float*)d_in[1];
    const float* c1   = (const float*)d_in[2];
    const float* c2   = (const float*)d_in[3];
    const float* c3   = (const float*)d_in[4];
    const float* c4   = (const float*)d_in[5];
    const float* bias = (const float*)d_in[6];
    float* out = (float*)d_out;

    const int n_tokens = in_sizes[0] / 4096;

    cudaFuncSetAttribute(tt_mma_kernel,
                         cudaFuncAttributeMaxDynamicSharedMemorySize, SMEM_BYTES);

    tt_merge_kernel<<<32, 256>>>(c0, c1, c2, c3, c4);

    const int grid = (n_tokens + 3) / 4;
    tt_mma_kernel<<<grid, 256, SMEM_BYTES>>>(x, bias, out, n_tokens);
}